// round 5
// baseline (speedup 1.0000x reference)
#include <cuda_runtime.h>
#include <math.h>
#include <stdint.h>

// Problem constants
#define BATCH 64
#define LDIM  1024
#define FFDIM 8192
#define HDIM  256
#define RDIM  4
#define EPSC  1e-4f

// Scratch
__device__ float g_mod[BATCH * FFDIM];     // 2 MB, layout [b][f]
__device__ float g_scale[BATCH * 4];
__device__ float g_weff[RDIM];
__device__ float g_beff;
__device__ float g_magpart[BATCH * 16];

// ---------------------------------------------------------------------------
// tf32 helpers (family-portable: mma.sync sm_80+)
// ---------------------------------------------------------------------------
__device__ __forceinline__ void tf32_split(float v, uint32_t& hi, uint32_t& lo)
{
    uint32_t h;
    asm("cvt.rna.tf32.f32 %0, %1;" : "=r"(h) : "f"(v));
    float r = v - __uint_as_float(h);
    asm("cvt.rna.tf32.f32 %0, %1;" : "=r"(lo) : "f"(r));
    hi = h;
}

__device__ __forceinline__ void mma8(float* d, const uint32_t* a, const uint32_t* b)
{
    asm volatile(
        "mma.sync.aligned.m16n8k8.row.col.f32.tf32.tf32.f32 "
        "{%0,%1,%2,%3}, {%4,%5,%6,%7}, {%8,%9}, {%0,%1,%2,%3};"
        : "+f"(d[0]), "+f"(d[1]), "+f"(d[2]), "+f"(d[3])
        : "r"(a[0]), "r"(a[1]), "r"(a[2]), "r"(a[3]), "r"(b[0]), "r"(b[1]));
}

// split a float4 into 4 interleaved (hi,lo) uint2 and store as 2x uint4
__device__ __forceinline__ void store_split4(uint2* dst, float4 v)
{
    uint32_t h0, l0, h1, l1, h2, l2, h3, l3;
    tf32_split(v.x, h0, l0);
    tf32_split(v.y, h1, l1);
    tf32_split(v.z, h2, l2);
    tf32_split(v.w, h3, l3);
    *reinterpret_cast<uint4*>(dst)     = make_uint4(h0, l0, h1, l1);
    *reinterpret_cast<uint4*>(dst + 2) = make_uint4(h2, l2, h3, l3);
}

// ---------------------------------------------------------------------------
// Kernel 1: fused GEMM pair + silu via mma.sync tf32 (3xTF32, split-at-store).
// CTA tile: M=64 f-rows x N=64 batch, K in 32-wide tiles, double buffer.
// smem tiles hold interleaved (hi,lo) uint2 per element; stride 36 uint2.
// ---------------------------------------------------------------------------
#define TSTR8  36                    // row stride in uint2 units (==4 mod 16)
#define TILE8  (64 * TSTR8)          // 2304 uint2 per tile
#define STAGE8 (3 * TILE8)           // Wt + Wg + x
#define GEMM_SMEM_BYTES (2 * STAGE8 * 8)   // 110592 B

__global__ void __launch_bounds__(128, 1)
k_gemm_mma(const float* __restrict__ x,
           const float* __restrict__ Wt,
           const float* __restrict__ Wg)
{
    extern __shared__ uint2 smem2[];
    const int t    = threadIdx.x;
    const int warp = t >> 5, lane = t & 31;
    const int gid  = lane >> 2, tig = lane & 3;
    const int mb   = (warp & 1) * 32;     // warp M offset (f)
    const int nb   = (warp >> 1) * 32;    // warp N offset (batch)
    const int f0   = blockIdx.x * 64;

    const float4* Wt4 = reinterpret_cast<const float4*>(Wt);
    const float4* Wg4 = reinterpret_cast<const float4*>(Wg);
    const float4* X4  = reinterpret_cast<const float4*>(x);

    float acc[2][2][4][4];
#pragma unroll
    for (int g = 0; g < 2; g++)
#pragma unroll
        for (int i = 0; i < 2; i++)
#pragma unroll
            for (int j = 0; j < 4; j++)
#pragma unroll
                for (int c = 0; c < 4; c++) acc[g][i][j][c] = 0.f;

    float4 wtp[4], wgp[4], xp[4];
#pragma unroll
    for (int q = 0; q < 4; q++) {
        int idx = q * 128 + t, row = idx >> 3, col = idx & 7;
        wtp[q] = Wt4[(size_t)(f0 + row) * 256 + col];
        wgp[q] = Wg4[(size_t)(f0 + row) * 256 + col];
        xp[q]  = X4[(size_t)row * 256 + col];
    }

    for (int kt = 0; kt < 32; ++kt) {
        uint2* st = smem2 + (kt & 1) * STAGE8;
#pragma unroll
        for (int q = 0; q < 4; q++) {
            int idx = q * 128 + t, row = idx >> 3, c = (idx & 7) * 4;
            store_split4(st + row * TSTR8 + c,              wtp[q]);
            store_split4(st + TILE8 + row * TSTR8 + c,      wgp[q]);
            store_split4(st + 2 * TILE8 + row * TSTR8 + c,  xp[q]);
        }
        __syncthreads();

        if (kt + 1 < 32) {
            const size_t ko = (size_t)(kt + 1) * 8;
#pragma unroll
            for (int q = 0; q < 4; q++) {
                int idx = q * 128 + t, row = idx >> 3, col = idx & 7;
                wtp[q] = Wt4[(size_t)(f0 + row) * 256 + ko + col];
                wgp[q] = Wg4[(size_t)(f0 + row) * 256 + ko + col];
                xp[q]  = X4[(size_t)row * 256 + ko + col];
            }
        }

        const uint2* Xb = st + 2 * TILE8;
#pragma unroll
        for (int ks = 0; ks < 4; ++ks) {
            const int ko = ks * 8;
            uint32_t Ah[2][2][4], Al[2][2][4], Bh[4][2], Bl[4][2];
#pragma unroll
            for (int g = 0; g < 2; ++g) {
                const uint2* Wb = st + g * TILE8;
#pragma unroll
                for (int i = 0; i < 2; ++i) {
                    int base = (mb + i * 16 + gid) * TSTR8 + ko + tig;
                    uint2 u0 = Wb[base];
                    uint2 u1 = Wb[base + 8 * TSTR8];
                    uint2 u2 = Wb[base + 4];
                    uint2 u3 = Wb[base + 8 * TSTR8 + 4];
                    Ah[g][i][0] = u0.x; Al[g][i][0] = u0.y;
                    Ah[g][i][1] = u1.x; Al[g][i][1] = u1.y;
                    Ah[g][i][2] = u2.x; Al[g][i][2] = u2.y;
                    Ah[g][i][3] = u3.x; Al[g][i][3] = u3.y;
                }
            }
#pragma unroll
            for (int j = 0; j < 4; ++j) {
                int base = (nb + j * 8 + gid) * TSTR8 + ko + tig;
                uint2 v0 = Xb[base];
                uint2 v1 = Xb[base + 4];
                Bh[j][0] = v0.x; Bl[j][0] = v0.y;
                Bh[j][1] = v1.x; Bl[j][1] = v1.y;
            }
#pragma unroll
            for (int g = 0; g < 2; ++g)
#pragma unroll
                for (int i = 0; i < 2; ++i)
#pragma unroll
                    for (int j = 0; j < 4; ++j) {
                        mma8(acc[g][i][j], Ah[g][i], Bh[j]);
                        mma8(acc[g][i][j], Ah[g][i], Bl[j]);
                        mma8(acc[g][i][j], Al[g][i], Bh[j]);
                    }
        }
    }

    // silu epilogue -> smem transpose -> coalesced float4 stores
    float* sOut = reinterpret_cast<float*>(smem2);   // 64 (b) x 68-stride (f)
#pragma unroll
    for (int i = 0; i < 2; ++i)
#pragma unroll
        for (int j = 0; j < 4; ++j)
#pragma unroll
            for (int c = 0; c < 4; ++c) {
                float tv = acc[0][i][j][c];
                float gv = acc[1][i][j][c];
                float o  = tv * __fdividef(gv, 1.0f + __expf(-gv));
                int fl = mb + i * 16 + gid + ((c >> 1) << 3);
                int bl = nb + j * 8 + 2 * tig + (c & 1);
                sOut[bl * 68 + fl] = o;
            }
    __syncthreads();

#pragma unroll
    for (int v = 0; v < 8; ++v) {
        int idx = v * 128 + t;
        int row = idx >> 4, q = idx & 15;
        float4 val = *reinterpret_cast<const float4*>(sOut + row * 68 + q * 4);
        *reinterpret_cast<float4*>(&g_mod[(size_t)row * FFDIM + f0 + q * 4]) = val;
    }
}

// ---------------------------------------------------------------------------
// Block reduction helper (256 threads)
// ---------------------------------------------------------------------------
__device__ __forceinline__ float block_reduce_256(float v, float* sh)
{
#pragma unroll
    for (int o = 16; o > 0; o >>= 1) v += __shfl_xor_sync(0xFFFFFFFFu, v, o);
    int w = threadIdx.x >> 5;
    if ((threadIdx.x & 31) == 0) sh[w] = v;
    __syncthreads();
    if (threadIdx.x < 8) {
        v = sh[threadIdx.x];
#pragma unroll
        for (int o = 4; o > 0; o >>= 1) v += __shfl_xor_sync(0x000000FFu, v, o);
    }
    return v;
}

// ---------------------------------------------------------------------------
// Kernel 2: per-(b,k) normalization scales + conv reductions
// ---------------------------------------------------------------------------
__global__ void k_scale(const float* __restrict__ conv_w,
                        const float* __restrict__ conv_b)
{
    __shared__ float sh[8];
    const int g = blockIdx.x;                 // g = b*4 + k
    const float4* p4 = reinterpret_cast<const float4*>(g_mod + (size_t)g * 2048);
    float4 a = p4[threadIdx.x];
    float4 c = p4[threadIdx.x + 256];
    float s = fabsf(a.x) + fabsf(a.y) + fabsf(a.z) + fabsf(a.w)
            + fabsf(c.x) + fabsf(c.y) + fabsf(c.z) + fabsf(c.w);
    s = block_reduce_256(s, sh);
    if (threadIdx.x == 0)
        g_scale[g] = rsqrtf(s * (1.0f / 2048.0f) + EPSC);

    if (g == 0) {
        if (threadIdx.x < RDIM) {
            float w = 0.f;
#pragma unroll
            for (int i = 0; i < RDIM; i++) w += conv_w[i * RDIM + threadIdx.x];
            g_weff[threadIdx.x] = w;
        }
        if (threadIdx.x == RDIM) {
            float b = 0.f;
#pragma unroll
            for (int i = 0; i < RDIM; i++) b += conv_b[i];
            g_beff = b;
        }
    }
}

// ---------------------------------------------------------------------------
// Kernel 3: per-batch magnitude partial sums.
// grid (8, B); block 256. Each thread: 16 il-rows x 2 pixels.
// ---------------------------------------------------------------------------
__global__ void __launch_bounds__(256)
k_mag(const float* __restrict__ ws, const float* __restrict__ wm)
{
    __shared__ float wa[32 * 8];     // [il][k*4+r]
    __shared__ float sh[8];

    const int b   = blockIdx.y;
    const int il0 = blockIdx.x * 32;
    const int t   = threadIdx.x;

    {
        int il = t & 31, k = (t >> 5) & 1, r = t >> 6;
        wa[il * 8 + k * 4 + r] =
            g_weff[r] * g_scale[b * 4 + k]
            * g_mod[(size_t)b * FFDIM + k * 2048 + r * 512 + il0 + il];
    }

    const int tj = t & 127, ti = t >> 7;
    const int j0 = 2 * tj;

    float2 sb0[4], sb1[4];
    {
        float s0 = g_scale[b * 4 + 0], s1 = g_scale[b * 4 + 1];
#pragma unroll
        for (int r = 0; r < 4; r++) {
            float2 v0 = *reinterpret_cast<const float2*>(
                &g_mod[(size_t)b * FFDIM + 0 * 2048 + r * 512 + HDIM + j0]);
            float2 v1 = *reinterpret_cast<const float2*>(
                &g_mod[(size_t)b * FFDIM + 1 * 2048 + r * 512 + HDIM + j0]);
            sb0[r] = make_float2(v0.x * s0, v0.y * s0);
            sb1[r] = make_float2(v1.x * s1, v1.y * s1);
        }
    }
    __syncthreads();

    const float be = g_beff;
    float sum = 0.f;
#pragma unroll
    for (int s = 0; s < 16; s++) {
        const int il  = ti * 16 + s;
        const int pix = ((il0 + il) << 8) + j0;
        float4 w0 = *reinterpret_cast<const float4*>(&wa[il * 8]);
        float4 w1 = *reinterpret_cast<const float4*>(&wa[il * 8 + 4]);
        float a0x = be, a0y = be, a1x = be, a1y = be;
        a0x = fmaf(w0.x, sb0[0].x, a0x); a0y = fmaf(w0.x, sb0[0].y, a0y);
        a0x = fmaf(w0.y, sb0[1].x, a0x); a0y = fmaf(w0.y, sb0[1].y, a0y);
        a0x = fmaf(w0.z, sb0[2].x, a0x); a0y = fmaf(w0.z, sb0[2].y, a0y);
        a0x = fmaf(w0.w, sb0[3].x, a0x); a0y = fmaf(w0.w, sb0[3].y, a0y);
        a1x = fmaf(w1.x, sb1[0].x, a1x); a1y = fmaf(w1.x, sb1[0].y, a1y);
        a1x = fmaf(w1.y, sb1[1].x, a1x); a1y = fmaf(w1.y, sb1[1].y, a1y);
        a1x = fmaf(w1.z, sb1[2].x, a1x); a1y = fmaf(w1.z, sb1[2].y, a1y);
        a1x = fmaf(w1.w, sb1[3].x, a1x); a1y = fmaf(w1.w, sb1[3].y, a1y);
        float2 wm0 = *reinterpret_cast<const float2*>(&wm[pix]);
        float2 wm1 = *reinterpret_cast<const float2*>(&wm[65536 + pix]);
        float m0x = wm0.x * a0x, m0y = wm0.y * a0y;
        float m1x = wm1.x * a1x, m1y = wm1.y * a1y;
        float4 A1 = *reinterpret_cast<const float4*>(&ws[131072 + 2 * pix]);
        float rex = A1.x * m0x - A1.y * m1x;
        float imx = A1.x * m1x - A1.y * m0x;
        float rey = A1.z * m0y - A1.w * m1y;
        float imy = A1.z * m1y - A1.w * m0y;
        sum += sqrtf(fmaf(rex, rex, fmaf(imx, imx, EPSC)));
        sum += sqrtf(fmaf(rey, rey, fmaf(imy, imy, EPSC)));
    }
    sum = block_reduce_256(sum, sh);
    if (t == 0) g_magpart[b * 8 + blockIdx.x] = sum;
}

// ---------------------------------------------------------------------------
// Kernel 4: final output. grid (8, B); block 256; 16 il x 2 px per thread.
// ---------------------------------------------------------------------------
__global__ void __launch_bounds__(256)
k_final(const float* __restrict__ ws, const float* __restrict__ wm,
        float* __restrict__ out)
{
    __shared__ float wa[32 * 16];    // [il][k*4+r]

    const int b   = blockIdx.y;
    const int il0 = blockIdx.x * 32;
    const int t   = threadIdx.x;

#pragma unroll
    for (int q = 0; q < 2; q++) {
        int idx = t + q * 256;
        int il = idx & 31, k = (idx >> 5) & 3, r = idx >> 7;
        wa[il * 16 + k * 4 + r] =
            g_weff[r] * g_scale[b * 4 + k]
            * g_mod[(size_t)b * FFDIM + k * 2048 + r * 512 + il0 + il];
    }

    const int tj = t & 127, ti = t >> 7;
    const int j0 = 2 * tj;

    float2 sbv[4][4];
#pragma unroll
    for (int k = 0; k < 4; k++) {
        float sc = g_scale[b * 4 + k];
#pragma unroll
        for (int r = 0; r < 4; r++) {
            float2 v = *reinterpret_cast<const float2*>(
                &g_mod[(size_t)b * FFDIM + k * 2048 + r * 512 + HDIM + j0]);
            sbv[k][r] = make_float2(v.x * sc, v.y * sc);
        }
    }
    __syncthreads();

    float msum = 0.f;
#pragma unroll
    for (int q = 0; q < 8; q++) msum += g_magpart[b * 8 + q];
    const float inv = rsqrtf(msum * (1.0f / 65536.0f) + EPSC);
    const float be = g_beff;

#pragma unroll
    for (int s = 0; s < 16; s++) {
        const int il  = ti * 16 + s;
        const int pix = ((il0 + il) << 8) + j0;
        float mx[4], my[4];
#pragma unroll
        for (int k = 0; k < 4; k++) {
            float4 wk = *reinterpret_cast<const float4*>(&wa[il * 16 + k * 4]);
            float ax = be, ay = be;
            ax = fmaf(wk.x, sbv[k][0].x, ax); ay = fmaf(wk.x, sbv[k][0].y, ay);
            ax = fmaf(wk.y, sbv[k][1].x, ax); ay = fmaf(wk.y, sbv[k][1].y, ay);
            ax = fmaf(wk.z, sbv[k][2].x, ax); ay = fmaf(wk.z, sbv[k][2].y, ay);
            ax = fmaf(wk.w, sbv[k][3].x, ax); ay = fmaf(wk.w, sbv[k][3].y, ay);
            float2 wmv = *reinterpret_cast<const float2*>(&wm[(k << 16) + pix]);
            mx[k] = wmv.x * ax; my[k] = wmv.y * ay;
        }
        float4 A0 = *reinterpret_cast<const float4*>(&ws[2 * pix]);
        float4 A1 = *reinterpret_cast<const float4*>(&ws[131072 + 2 * pix]);

        float rex = A1.x * mx[0] - A1.y * mx[1];
        float imx = A1.x * mx[1] - A1.y * mx[0];
        float mwreX = fmaf(rex, inv, A0.x);
        float mwimX = fmaf(imx, inv, A0.y);
        float denX = sqrtf(fmaf(mx[2], mx[2], fmaf(mx[3], mx[3], EPSC)));
        float ox = __fdividef(fmaf(mwreX, mx[2], mwimX * mx[3]), denX);

        float rey = A1.z * my[0] - A1.w * my[1];
        float imy = A1.z * my[1] - A1.w * my[0];
        float mwreY = fmaf(rey, inv, A0.z);
        float mwimY = fmaf(imy, inv, A0.w);
        float denY = sqrtf(fmaf(my[2], my[2], fmaf(my[3], my[3], EPSC)));
        float oy = __fdividef(fmaf(mwreY, my[2], mwimY * my[3]), denY);

        *reinterpret_cast<float2*>(&out[((size_t)b << 16) + pix]) =
            make_float2(ox, oy);
    }
}

// ---------------------------------------------------------------------------
// Launch
// ---------------------------------------------------------------------------
extern "C" void kernel_launch(void* const* d_in, const int* in_sizes, int n_in,
                              void* d_out, int out_size)
{
    const float* x      = (const float*)d_in[0];
    const float* Wt     = (const float*)d_in[1];
    const float* Wg     = (const float*)d_in[2];
    const float* ws     = (const float*)d_in[3];
    const float* wm     = (const float*)d_in[4];
    const float* conv_w = (const float*)d_in[5];
    const float* conv_b = (const float*)d_in[6];
    float* out = (float*)d_out;

    cudaFuncSetAttribute(k_gemm_mma,
                         cudaFuncAttributeMaxDynamicSharedMemorySize,
                         GEMM_SMEM_BYTES);

    k_gemm_mma<<<FFDIM / 64, 128, GEMM_SMEM_BYTES>>>(x, Wt, Wg);
    k_scale<<<BATCH * 4, 256>>>(conv_w, conv_b);
    k_mag<<<dim3(8, BATCH), 256>>>(ws, wm);
    k_final<<<dim3(8, BATCH), 256>>>(ws, wm, out);
}

// round 6
// speedup vs baseline: 1.3199x; 1.3199x over previous
#include <cuda_runtime.h>
#include <math.h>
#include <stdint.h>

// Problem constants
#define BATCH 64
#define LDIM  1024
#define FFDIM 8192
#define HDIM  256
#define RDIM  4
#define EPSC  1e-4f

// Scratch
__device__ float g_mod[BATCH * FFDIM];     // 2 MB, layout [b][f]
__device__ float g_scale[BATCH * 4];
__device__ float g_weff[RDIM];
__device__ float g_beff;
__device__ float g_magpart[BATCH * 16];

// ---------------------------------------------------------------------------
// tf32 helpers (family-portable: mma.sync sm_80+)
// ---------------------------------------------------------------------------
__device__ __forceinline__ void tf32_split(float v, uint32_t& hi, uint32_t& lo)
{
    uint32_t h;
    asm("cvt.rna.tf32.f32 %0, %1;" : "=r"(h) : "f"(v));
    float r = v - __uint_as_float(h);
    asm("cvt.rna.tf32.f32 %0, %1;" : "=r"(lo) : "f"(r));
    hi = h;
}

__device__ __forceinline__ void mma8(float* d, const uint32_t* a, const uint32_t* b)
{
    asm volatile(
        "mma.sync.aligned.m16n8k8.row.col.f32.tf32.tf32.f32 "
        "{%0,%1,%2,%3}, {%4,%5,%6,%7}, {%8,%9}, {%0,%1,%2,%3};"
        : "+f"(d[0]), "+f"(d[1]), "+f"(d[2]), "+f"(d[3])
        : "r"(a[0]), "r"(a[1]), "r"(a[2]), "r"(a[3]), "r"(b[0]), "r"(b[1]));
}

// ---------------------------------------------------------------------------
// Kernel 1: fused GEMM pair + silu via mma.sync tf32 (3xTF32, split-at-use).
// CTA tile: M=64 f-rows x N=64 batch, K in 32-wide tiles, double buffer.
// 256 threads = 8 warps; warp tile M=16 x N=32 (2 warps per SMSP).
// ---------------------------------------------------------------------------
#define TSTR   36                  // padded row stride (floats)
#define TILE_F (64 * TSTR)
#define STAGE_F (3 * TILE_F)       // Wt + Wg + x
#define GEMM_SMEM_BYTES (2 * STAGE_F * 4)   // 55296 B

__global__ void __launch_bounds__(256, 1)
k_gemm_mma(const float* __restrict__ x,
           const float* __restrict__ Wt,
           const float* __restrict__ Wg)
{
    extern __shared__ float smem[];
    const int t    = threadIdx.x;
    const int warp = t >> 5, lane = t & 31;
    const int gid  = lane >> 2, tig = lane & 3;
    const int mb   = (warp & 3) * 16;     // warp M offset (f), 4 positions
    const int nb   = (warp >> 2) * 32;    // warp N offset (batch), 2 positions
    const int f0   = blockIdx.x * 64;

    const float4* Wt4 = reinterpret_cast<const float4*>(Wt);
    const float4* Wg4 = reinterpret_cast<const float4*>(Wg);
    const float4* X4  = reinterpret_cast<const float4*>(x);

    float acc[2][4][4];
#pragma unroll
    for (int g = 0; g < 2; g++)
#pragma unroll
        for (int j = 0; j < 4; j++)
#pragma unroll
            for (int c = 0; c < 4; c++) acc[g][j][c] = 0.f;

    float4 wtp[2], wgp[2], xp[2];
#pragma unroll
    for (int q = 0; q < 2; q++) {
        int idx = q * 256 + t, row = idx >> 3, col = idx & 7;
        wtp[q] = Wt4[(size_t)(f0 + row) * 256 + col];
        wgp[q] = Wg4[(size_t)(f0 + row) * 256 + col];
        xp[q]  = X4[(size_t)row * 256 + col];
    }

    for (int kt = 0; kt < 32; ++kt) {
        float* st = smem + (kt & 1) * STAGE_F;
#pragma unroll
        for (int q = 0; q < 2; q++) {
            int idx = q * 256 + t, row = idx >> 3, col = idx & 7;
            *reinterpret_cast<float4*>(st + row * TSTR + col * 4)              = wtp[q];
            *reinterpret_cast<float4*>(st + TILE_F + row * TSTR + col * 4)     = wgp[q];
            *reinterpret_cast<float4*>(st + 2 * TILE_F + row * TSTR + col * 4) = xp[q];
        }
        __syncthreads();

        if (kt + 1 < 32) {
            const size_t ko = (size_t)(kt + 1) * 8;
#pragma unroll
            for (int q = 0; q < 2; q++) {
                int idx = q * 256 + t, row = idx >> 3, col = idx & 7;
                wtp[q] = Wt4[(size_t)(f0 + row) * 256 + ko + col];
                wgp[q] = Wg4[(size_t)(f0 + row) * 256 + ko + col];
                xp[q]  = X4[(size_t)row * 256 + ko + col];
            }
        }

        const float* Xb = st + 2 * TILE_F;
#pragma unroll
        for (int ks = 0; ks < 4; ++ks) {
            const int ko = ks * 8;
            uint32_t Ah[2][4], Al[2][4], Bh[4][2], Bl[4][2];
#pragma unroll
            for (int g = 0; g < 2; ++g) {
                const float* Wb = st + g * TILE_F;
                int r0 = mb + gid;
                float v0 = Wb[r0 * TSTR + ko + tig];
                float v1 = Wb[(r0 + 8) * TSTR + ko + tig];
                float v2 = Wb[r0 * TSTR + ko + tig + 4];
                float v3 = Wb[(r0 + 8) * TSTR + ko + tig + 4];
                tf32_split(v0, Ah[g][0], Al[g][0]);
                tf32_split(v1, Ah[g][1], Al[g][1]);
                tf32_split(v2, Ah[g][2], Al[g][2]);
                tf32_split(v3, Ah[g][3], Al[g][3]);
            }
#pragma unroll
            for (int j = 0; j < 4; ++j) {
                int base = (nb + j * 8 + gid) * TSTR + ko + tig;
                float v0 = Xb[base];
                float v1 = Xb[base + 4];
                tf32_split(v0, Bh[j][0], Bl[j][0]);
                tf32_split(v1, Bh[j][1], Bl[j][1]);
            }
#pragma unroll
            for (int g = 0; g < 2; ++g)
#pragma unroll
                for (int j = 0; j < 4; ++j) {
                    mma8(acc[g][j], Ah[g], Bh[j]);
                    mma8(acc[g][j], Ah[g], Bl[j]);
                    mma8(acc[g][j], Al[g], Bh[j]);
                }
        }
    }

    // silu epilogue -> smem transpose -> coalesced float4 stores
    float* sOut = smem;   // 64 (b) x 68-stride (f), fits in stage 0
#pragma unroll
    for (int j = 0; j < 4; ++j)
#pragma unroll
        for (int c = 0; c < 4; ++c) {
            float tv = acc[0][j][c];
            float gv = acc[1][j][c];
            float o  = tv * __fdividef(gv, 1.0f + __expf(-gv));
            int fl = mb + gid + ((c >> 1) << 3);
            int bl = nb + j * 8 + 2 * tig + (c & 1);
            sOut[bl * 68 + fl] = o;
        }
    __syncthreads();

#pragma unroll
    for (int v = 0; v < 4; ++v) {
        int idx = v * 256 + t;
        int row = idx >> 4, q = idx & 15;
        float4 val = *reinterpret_cast<const float4*>(sOut + row * 68 + q * 4);
        *reinterpret_cast<float4*>(&g_mod[(size_t)row * FFDIM + f0 + q * 4]) = val;
    }
}

// ---------------------------------------------------------------------------
// Block reduction helper (256 threads)
// ---------------------------------------------------------------------------
__device__ __forceinline__ float block_reduce_256(float v, float* sh)
{
#pragma unroll
    for (int o = 16; o > 0; o >>= 1) v += __shfl_xor_sync(0xFFFFFFFFu, v, o);
    int w = threadIdx.x >> 5;
    if ((threadIdx.x & 31) == 0) sh[w] = v;
    __syncthreads();
    if (threadIdx.x < 8) {
        v = sh[threadIdx.x];
#pragma unroll
        for (int o = 4; o > 0; o >>= 1) v += __shfl_xor_sync(0x000000FFu, v, o);
    }
    return v;
}

// ---------------------------------------------------------------------------
// Kernel 2: per-(b,k) normalization scales + conv reductions
// ---------------------------------------------------------------------------
__global__ void k_scale(const float* __restrict__ conv_w,
                        const float* __restrict__ conv_b)
{
    __shared__ float sh[8];
    const int g = blockIdx.x;                 // g = b*4 + k
    const float4* p4 = reinterpret_cast<const float4*>(g_mod + (size_t)g * 2048);
    float4 a = p4[threadIdx.x];
    float4 c = p4[threadIdx.x + 256];
    float s = fabsf(a.x) + fabsf(a.y) + fabsf(a.z) + fabsf(a.w)
            + fabsf(c.x) + fabsf(c.y) + fabsf(c.z) + fabsf(c.w);
    s = block_reduce_256(s, sh);
    if (threadIdx.x == 0)
        g_scale[g] = rsqrtf(s * (1.0f / 2048.0f) + EPSC);

    if (g == 0) {
        if (threadIdx.x < RDIM) {
            float w = 0.f;
#pragma unroll
            for (int i = 0; i < RDIM; i++) w += conv_w[i * RDIM + threadIdx.x];
            g_weff[threadIdx.x] = w;
        }
        if (threadIdx.x == RDIM) {
            float b = 0.f;
#pragma unroll
            for (int i = 0; i < RDIM; i++) b += conv_b[i];
            g_beff = b;
        }
    }
}

// ---------------------------------------------------------------------------
// Kernel 3: per-batch magnitude partial sums. (Round-4 proven version)
// ---------------------------------------------------------------------------
__global__ void __launch_bounds__(256)
k_mag(const float* __restrict__ ws, const float* __restrict__ wm)
{
    __shared__ float4 wa4[16][2];    // [il][k] quads over r
    __shared__ float  sh[8];

    const int b  = blockIdx.y;
    const int i0 = blockIdx.x * 16;
    const int t  = threadIdx.x;

    if (t < 128) {
        int k = t >> 6, r = (t >> 4) & 3, il = t & 15;
        reinterpret_cast<float*>(wa4)[il * 8 + k * 4 + r] =
            g_weff[r] * g_scale[b * 4 + k]
            * g_mod[(size_t)b * FFDIM + k * 2048 + r * 512 + (i0 + il)];
    }

    float sb0[4], sb1[4];
    {
        float s0 = g_scale[b * 4 + 0], s1 = g_scale[b * 4 + 1];
#pragma unroll
        for (int r = 0; r < 4; r++) {
            sb0[r] = s0 * g_mod[(size_t)b * FFDIM + 0 * 2048 + r * 512 + HDIM + t];
            sb1[r] = s1 * g_mod[(size_t)b * FFDIM + 1 * 2048 + r * 512 + HDIM + t];
        }
    }
    __syncthreads();

    const float be = g_beff;
    float sum = 0.f;
#pragma unroll
    for (int il = 0; il < 16; il++) {
        const int pix = ((i0 + il) << 8) + t;
        float4 w0 = wa4[il][0];
        float4 w1 = wa4[il][1];
        float m0 = be, m1 = be;
        m0 = fmaf(w0.x, sb0[0], m0); m0 = fmaf(w0.y, sb0[1], m0);
        m0 = fmaf(w0.z, sb0[2], m0); m0 = fmaf(w0.w, sb0[3], m0);
        m1 = fmaf(w1.x, sb1[0], m1); m1 = fmaf(w1.y, sb1[1], m1);
        m1 = fmaf(w1.z, sb1[2], m1); m1 = fmaf(w1.w, sb1[3], m1);
        m0 *= wm[pix];
        m1 *= wm[65536 + pix];
        float2 A1 = *reinterpret_cast<const float2*>(&ws[131072 + 2 * pix]);
        float re = A1.x * m0 - A1.y * m1;
        float im = A1.x * m1 - A1.y * m0;
        sum += sqrtf(fmaf(re, re, fmaf(im, im, EPSC)));
    }
    sum = block_reduce_256(sum, sh);
    if (t == 0) g_magpart[b * 16 + blockIdx.x] = sum;
}

// ---------------------------------------------------------------------------
// Kernel 4: final output. (Round-4 proven version)
// ---------------------------------------------------------------------------
__global__ void __launch_bounds__(256)
k_final(const float* __restrict__ ws, const float* __restrict__ wm,
        float* __restrict__ out)
{
    __shared__ float4 wa4[16][4];    // [il][k]

    const int b  = blockIdx.y;
    const int i0 = blockIdx.x * 16;
    const int t  = threadIdx.x;

    {
        int k = t >> 6, r = (t >> 4) & 3, il = t & 15;
        reinterpret_cast<float*>(wa4)[il * 16 + k * 4 + r] =
            g_weff[r] * g_scale[b * 4 + k]
            * g_mod[(size_t)b * FFDIM + k * 2048 + r * 512 + (i0 + il)];
    }

    float sbv[4][4];
#pragma unroll
    for (int k = 0; k < 4; k++) {
        float sc = g_scale[b * 4 + k];
#pragma unroll
        for (int r = 0; r < 4; r++)
            sbv[k][r] = sc * g_mod[(size_t)b * FFDIM + k * 2048 + r * 512 + HDIM + t];
    }
    __syncthreads();

    float msum = 0.f;
#pragma unroll
    for (int q = 0; q < 16; q++) msum += g_magpart[b * 16 + q];
    const float inv = rsqrtf(msum * (1.0f / 65536.0f) + EPSC);
    const float be = g_beff;

#pragma unroll
    for (int il = 0; il < 16; il++) {
        const int pix = ((i0 + il) << 8) + t;
        float m[4];
#pragma unroll
        for (int k = 0; k < 4; k++) {
            float4 wk = wa4[il][k];
            float acc = be;
            acc = fmaf(wk.x, sbv[k][0], acc);
            acc = fmaf(wk.y, sbv[k][1], acc);
            acc = fmaf(wk.z, sbv[k][2], acc);
            acc = fmaf(wk.w, sbv[k][3], acc);
            m[k] = wm[(k << 16) + pix] * acc;
        }
        float2 A0 = *reinterpret_cast<const float2*>(&ws[2 * pix]);
        float2 A1 = *reinterpret_cast<const float2*>(&ws[131072 + 2 * pix]);
        float re = A1.x * m[0] - A1.y * m[1];
        float im = A1.x * m[1] - A1.y * m[0];
        float mwre = fmaf(re, inv, A0.x);
        float mwim = fmaf(im, inv, A0.y);
        float den = sqrtf(fmaf(m[2], m[2], fmaf(m[3], m[3], EPSC)));
        out[((size_t)b << 16) + pix] =
            __fdividef(fmaf(mwre, m[2], mwim * m[3]), den);
    }
}

// ---------------------------------------------------------------------------
// Launch
// ---------------------------------------------------------------------------
extern "C" void kernel_launch(void* const* d_in, const int* in_sizes, int n_in,
                              void* d_out, int out_size)
{
    const float* x      = (const float*)d_in[0];
    const float* Wt     = (const float*)d_in[1];
    const float* Wg     = (const float*)d_in[2];
    const float* ws     = (const float*)d_in[3];
    const float* wm     = (const float*)d_in[4];
    const float* conv_w = (const float*)d_in[5];
    const float* conv_b = (const float*)d_in[6];
    float* out = (float*)d_out;

    cudaFuncSetAttribute(k_gemm_mma,
                         cudaFuncAttributeMaxDynamicSharedMemorySize,
                         GEMM_SMEM_BYTES);

    k_gemm_mma<<<FFDIM / 64, 256, GEMM_SMEM_BYTES>>>(x, Wt, Wg);
    k_scale<<<BATCH * 4, 256>>>(conv_w, conv_b);
    k_mag<<<dim3(16, BATCH), 256>>>(ws, wm);
    k_final<<<dim3(16, BATCH), 256>>>(ws, wm, out);
}